// round 1
// baseline (speedup 1.0000x reference)
#include <cuda_runtime.h>
#include <math.h>

#define B   2
#define NT  2048
#define DM  1024
#define H   16
#define HD  64
#define EPSF 1e-10f

// ---------------- scratch (device globals; no allocations) ----------------
__device__ float g_Q[(size_t)B*H*NT*HD];
__device__ float g_K[(size_t)B*H*NT*HD];
__device__ float g_V[(size_t)B*H*NT*HD];
__device__ float g_A[(size_t)B*H*NT*NT];     // scores -> attention (536 MB)
__device__ float g_P[(size_t)B*NT*NT];       // sinkhorn matrix (33.5 MB)
__device__ float g_ctx[(size_t)B*NT*DM];     // attention output context
__device__ float g_enth[(size_t)B*H*NT];     // per-(b,h,row) entropy
__device__ float g_colsum[(size_t)B*NT];

// ---------------------------------------------------------------------------
// NT GEMM: C[m][e] = sum_k A[m][k] * W[e][k] + bias[e]
// BM=BN=64, BK=16, 256 threads, 4x4 per thread.
// head_layout: 0 -> C row-major MxN; 1 -> C[((b*H+h)*NT+tok)*HD+hd]
// ---------------------------------------------------------------------------
__global__ __launch_bounds__(256)
void gemm_nt(const float* __restrict__ A, const float* __restrict__ W,
             const float* __restrict__ bias, float* __restrict__ C,
             int M, int N, int K, int head_layout)
{
    __shared__ float As[16][64];
    __shared__ float Bs[16][64];
    const int tid = threadIdx.x;
    const int tx = tid & 15, ty = tid >> 4;
    const int bm0 = blockIdx.y * 64, bn0 = blockIdx.x * 64;

    const int lr = tid >> 2;          // 0..63 row within tile
    const int lc = (tid & 3) * 4;     // 0,4,8,12 k within tile
    const float* Ag = A + (size_t)(bm0 + lr) * K + lc;
    const float* Wg = W + (size_t)(bn0 + lr) * K + lc;

    float acc[4][4] = {};

    for (int k0 = 0; k0 < K; k0 += 16) {
        float4 av = *(const float4*)(Ag + k0);
        float4 wv = *(const float4*)(Wg + k0);
        As[lc+0][lr] = av.x; As[lc+1][lr] = av.y; As[lc+2][lr] = av.z; As[lc+3][lr] = av.w;
        Bs[lc+0][lr] = wv.x; Bs[lc+1][lr] = wv.y; Bs[lc+2][lr] = wv.z; Bs[lc+3][lr] = wv.w;
        __syncthreads();
        #pragma unroll
        for (int k = 0; k < 16; k++) {
            float4 a4 = *(const float4*)&As[k][ty*4];
            float4 b4 = *(const float4*)&Bs[k][tx*4];
            float ar[4] = {a4.x, a4.y, a4.z, a4.w};
            float br[4] = {b4.x, b4.y, b4.z, b4.w};
            #pragma unroll
            for (int i = 0; i < 4; i++)
                #pragma unroll
                for (int j = 0; j < 4; j++)
                    acc[i][j] += ar[i] * br[j];
        }
        __syncthreads();
    }

    #pragma unroll
    for (int i = 0; i < 4; i++) {
        int m = bm0 + ty*4 + i;
        #pragma unroll
        for (int j = 0; j < 4; j++) {
            int e = bn0 + tx*4 + j;
            float v = acc[i][j] + bias[e];
            if (head_layout) {
                int bb = m >> 11, tok = m & 2047;
                int h = e >> 6, hd = e & 63;
                C[(((size_t)(bb*H + h)*NT + tok)*HD) + hd] = v;
            } else {
                C[(size_t)m * N + e] = v;
            }
        }
    }
}

// ---------------------------------------------------------------------------
// Scores: S[bh][i][j] = dot(Q_i,K_j)/8 - |pf_i - pf_j| * |pbs[h]|
// ---------------------------------------------------------------------------
__global__ __launch_bounds__(256)
void scores_kernel(const float* __restrict__ pbs, const int* __restrict__ perm)
{
    const int bh = blockIdx.z;
    const int b = bh >> 4, h = bh & 15;
    const int bi0 = blockIdx.y * 64, bj0 = blockIdx.x * 64;

    __shared__ float Qs[64][64];   // [k][i]
    __shared__ float Ks[64][64];   // [k][j]
    __shared__ float pfi[64], pfj[64];

    const int tid = threadIdx.x;
    const int tx = tid & 15, ty = tid >> 4;

    const float* Qg = g_Q + ((size_t)bh*NT + bi0) * HD;
    const float* Kg = g_K + ((size_t)bh*NT + bj0) * HD;

    const int lr = tid >> 2;          // 0..63
    const int lc = (tid & 3) * 16;    // 0,16,32,48
    #pragma unroll
    for (int u = 0; u < 4; u++) {
        float4 qv = *(const float4*)(Qg + (size_t)lr*HD + lc + u*4);
        float4 kv = *(const float4*)(Kg + (size_t)lr*HD + lc + u*4);
        Qs[lc+u*4+0][lr]=qv.x; Qs[lc+u*4+1][lr]=qv.y; Qs[lc+u*4+2][lr]=qv.z; Qs[lc+u*4+3][lr]=qv.w;
        Ks[lc+u*4+0][lr]=kv.x; Ks[lc+u*4+1][lr]=kv.y; Ks[lc+u*4+2][lr]=kv.z; Ks[lc+u*4+3][lr]=kv.w;
    }
    if (tid < 64)       pfi[tid]     = (float)perm[b*NT + bi0 + tid];
    else if (tid < 128) pfj[tid-64]  = (float)perm[b*NT + bj0 + (tid-64)];
    __syncthreads();

    float acc[4][4] = {};
    #pragma unroll 16
    for (int k = 0; k < 64; k++) {
        float4 a4 = *(const float4*)&Qs[k][ty*4];
        float4 b4 = *(const float4*)&Ks[k][tx*4];
        float ar[4] = {a4.x, a4.y, a4.z, a4.w};
        float br[4] = {b4.x, b4.y, b4.z, b4.w};
        #pragma unroll
        for (int i = 0; i < 4; i++)
            #pragma unroll
            for (int j = 0; j < 4; j++)
                acc[i][j] += ar[i] * br[j];
    }

    const float pb = fabsf(pbs[h]);
    #pragma unroll
    for (int i = 0; i < 4; i++) {
        int ii = ty*4 + i;
        #pragma unroll
        for (int j = 0; j < 4; j++) {
            int jj = tx*4 + j;
            float v = acc[i][j] * 0.125f - fabsf(pfi[ii] - pfj[jj]) * pb;
            g_A[((size_t)bh*NT + (bi0+ii))*NT + (bj0+jj)] = v;
        }
    }
}

// ---------------------------------------------------------------------------
// Row softmax (in place on g_A) + row entropy -> g_enth
// ---------------------------------------------------------------------------
__global__ __launch_bounds__(256)
void softmax_ent_kernel()
{
    const size_t row = blockIdx.x;              // 0 .. B*H*NT-1
    float* rp = g_A + row * NT;
    const int tid = threadIdx.x;
    __shared__ float red[256];

    float v[8];
    float mx = -INFINITY;
    #pragma unroll
    for (int s = 0; s < 8; s++) { v[s] = rp[tid + s*256]; mx = fmaxf(mx, v[s]); }

    red[tid] = mx; __syncthreads();
    for (int o = 128; o > 0; o >>= 1) { if (tid < o) red[tid] = fmaxf(red[tid], red[tid+o]); __syncthreads(); }
    mx = red[0]; __syncthreads();

    float sum = 0.f;
    #pragma unroll
    for (int s = 0; s < 8; s++) { v[s] = expf(v[s] - mx); sum += v[s]; }
    red[tid] = sum; __syncthreads();
    for (int o = 128; o > 0; o >>= 1) { if (tid < o) red[tid] += red[tid+o]; __syncthreads(); }
    sum = red[0]; __syncthreads();

    const float inv = 1.0f / sum;
    float ent = 0.f;
    #pragma unroll
    for (int s = 0; s < 8; s++) {
        float p = v[s] * inv;
        rp[tid + s*256] = p;
        ent -= p * logf(p + EPSF);
    }
    red[tid] = ent; __syncthreads();
    for (int o = 128; o > 0; o >>= 1) { if (tid < o) red[tid] += red[tid+o]; __syncthreads(); }
    if (tid == 0) g_enth[row] = red[0];
}

// ---------------------------------------------------------------------------
// AV: ctx[b, i, h*64+hd] = sum_j A[bh][i][j] * V[bh][j][hd]
// ---------------------------------------------------------------------------
__global__ __launch_bounds__(256)
void av_kernel()
{
    const int bh = blockIdx.z;
    const int b = bh >> 4, h = bh & 15;
    const int bi0 = blockIdx.y * 64;

    __shared__ float As[16][64];   // [k][i]
    __shared__ float Vs[16][64];   // [k][hd]
    const int tid = threadIdx.x;
    const int tx = tid & 15, ty = tid >> 4;

    const float* Ap = g_A + ((size_t)bh*NT + bi0) * NT;
    const float* Vp = g_V + (size_t)bh * NT * HD;

    const int lr = tid >> 2, lc = (tid & 3) * 4;     // A tile load
    const int vkr = tid >> 4, vc = (tid & 15) * 4;   // V tile load

    float acc[4][4] = {};

    for (int k0 = 0; k0 < NT; k0 += 16) {
        float4 av = *(const float4*)(Ap + (size_t)lr*NT + k0 + lc);
        As[lc+0][lr]=av.x; As[lc+1][lr]=av.y; As[lc+2][lr]=av.z; As[lc+3][lr]=av.w;
        *(float4*)&Vs[vkr][vc] = *(const float4*)(Vp + (size_t)(k0+vkr)*HD + vc);
        __syncthreads();
        #pragma unroll
        for (int k = 0; k < 16; k++) {
            float4 a4 = *(const float4*)&As[k][ty*4];
            float4 b4 = *(const float4*)&Vs[k][tx*4];
            float ar[4] = {a4.x, a4.y, a4.z, a4.w};
            float br[4] = {b4.x, b4.y, b4.z, b4.w};
            #pragma unroll
            for (int i = 0; i < 4; i++)
                #pragma unroll
                for (int j = 0; j < 4; j++)
                    acc[i][j] += ar[i] * br[j];
        }
        __syncthreads();
    }

    #pragma unroll
    for (int i = 0; i < 4; i++) {
        int tok = bi0 + ty*4 + i;
        #pragma unroll
        for (int j = 0; j < 4; j++) {
            int hd = tx*4 + j;
            g_ctx[((size_t)b*NT + tok)*DM + h*HD + hd] = acc[i][j];
        }
    }
}

// ---------------------------------------------------------------------------
// P = exp(log(mean_h A + EPS) / 0.1)
// ---------------------------------------------------------------------------
__global__ __launch_bounds__(256)
void build_P_kernel()
{
    size_t idx = (size_t)blockIdx.x * 256 + threadIdx.x;   // 0 .. B*NT*NT-1
    size_t b = idx / ((size_t)NT*NT);
    size_t rem = idx - b * (size_t)NT*NT;
    float s = 0.f;
    #pragma unroll
    for (int h = 0; h < H; h++)
        s += g_A[((size_t)(b*H + h))*NT*NT + rem];
    float avg = s * (1.0f / 16.0f);
    g_P[idx] = expf(logf(avg + EPSF) / 0.1f);
}

// ---------------------------------------------------------------------------
// Sinkhorn pieces
// ---------------------------------------------------------------------------
__global__ __launch_bounds__(256)
void rownorm_kernel()
{
    const size_t row = blockIdx.x;     // 0..B*NT-1
    float* rp = g_P + row * NT;
    const int tid = threadIdx.x;
    __shared__ float red[256];
    float v[8]; float s = 0.f;
    #pragma unroll
    for (int k = 0; k < 8; k++) { v[k] = rp[tid + k*256]; s += v[k]; }
    red[tid] = s; __syncthreads();
    for (int o = 128; o > 0; o >>= 1) { if (tid < o) red[tid] += red[tid+o]; __syncthreads(); }
    float inv = 1.0f / (red[0] + EPSF);
    #pragma unroll
    for (int k = 0; k < 8; k++) rp[tid + k*256] = v[k] * inv;
}

__global__ __launch_bounds__(256)
void colsum_kernel()
{
    const int j = blockIdx.x * 256 + threadIdx.x;   // 0..NT-1
    const int b = blockIdx.y;
    const float* p = g_P + (size_t)b*NT*NT + j;
    float s = 0.f;
    for (int i = 0; i < NT; i++) s += p[(size_t)i*NT];
    g_colsum[b*NT + j] = s;
}

__global__ __launch_bounds__(256)
void coldiv_kernel()
{
    size_t idx = (size_t)blockIdx.x * 256 + threadIdx.x;
    size_t b = idx / ((size_t)NT*NT);
    int j = (int)(idx % NT);
    g_P[idx] = g_P[idx] / (g_colsum[b*NT + j] + EPSF);
}

// ---------------------------------------------------------------------------
// Certainty update
// ---------------------------------------------------------------------------
__global__ __launch_bounds__(256)
void cert_kernel(const float* __restrict__ cert, const float* __restrict__ ctemp,
                 float* __restrict__ out)
{
    const int idx = blockIdx.x * 256 + threadIdx.x;  // 0..B*NT-1
    const int b = idx >> 11, i = idx & 2047;
    float s = 0.f;
    #pragma unroll
    for (int h = 0; h < H; h++) s += g_enth[(size_t)(b*H + h)*NT + i];
    float ent = s * (1.0f / 16.0f);
    float z = ctemp[0] * (logf(2048.0f) - ent);
    float cu = 1.0f / (1.0f + expf(-z));
    out[idx] = fmaxf(cert[idx], cu);
}

// ---------------------------------------------------------------------------
// Row argmax of P (first max wins) + gather of old permutation
// ---------------------------------------------------------------------------
__global__ __launch_bounds__(256)
void argmax_gather_kernel(const int* __restrict__ perm, float* __restrict__ out)
{
    const int row = blockIdx.x;          // 0..B*NT-1
    const int b = row >> 11;
    const float* rp = g_P + (size_t)row * NT;
    const int tid = threadIdx.x;
    __shared__ float bv[256];
    __shared__ int   bi[256];

    float best = -INFINITY; int bj = NT;
    #pragma unroll
    for (int s = 0; s < 8; s++) {
        int j = tid + s*256;
        float v = rp[j];
        if (v > best) { best = v; bj = j; }
    }
    bv[tid] = best; bi[tid] = bj; __syncthreads();
    for (int o = 128; o > 0; o >>= 1) {
        if (tid < o) {
            if (bv[tid+o] > bv[tid] || (bv[tid+o] == bv[tid] && bi[tid+o] < bi[tid])) {
                bv[tid] = bv[tid+o]; bi[tid] = bi[tid+o];
            }
        }
        __syncthreads();
    }
    if (tid == 0) out[row] = (float)perm[(size_t)b*NT + bi[0]];
}

// ---------------------------------------------------------------------------
extern "C" void kernel_launch(void* const* d_in, const int* in_sizes, int n_in,
                              void* d_out, int out_size)
{
    const float* x     = (const float*)d_in[0];
    const float* cert  = (const float*)d_in[1];
    const int*   perm  = (const int*)  d_in[2];   // jax x64 disabled -> int32
    const float* Wq    = (const float*)d_in[3];
    const float* bq    = (const float*)d_in[4];
    const float* Wk    = (const float*)d_in[5];
    const float* bk    = (const float*)d_in[6];
    const float* Wv    = (const float*)d_in[7];
    const float* bv    = (const float*)d_in[8];
    const float* Wo    = (const float*)d_in[9];
    const float* bo    = (const float*)d_in[10];
    const float* pbs   = (const float*)d_in[11];
    const float* ctemp = (const float*)d_in[12];
    float* out = (float*)d_out;

    float *pQ, *pK, *pV, *pCtx;
    cudaGetSymbolAddress((void**)&pQ,   g_Q);
    cudaGetSymbolAddress((void**)&pK,   g_K);
    cudaGetSymbolAddress((void**)&pV,   g_V);
    cudaGetSymbolAddress((void**)&pCtx, g_ctx);

    const int M = B * NT;                 // 4096

    // QKV projections into head layout
    dim3 gProj(DM/64, M/64);              // (16, 64)
    gemm_nt<<<gProj, 256>>>(x, Wq, bq, pQ, M, DM, DM, 1);
    gemm_nt<<<gProj, 256>>>(x, Wk, bk, pK, M, DM, DM, 1);
    gemm_nt<<<gProj, 256>>>(x, Wv, bv, pV, M, DM, DM, 1);

    // Scores with permutation-distance bias
    dim3 gScore(NT/64, NT/64, B*H);       // (32, 32, 32)
    scores_kernel<<<gScore, 256>>>(pbs, perm);

    // Softmax + entropy (in place)
    softmax_ent_kernel<<<B*H*NT, 256>>>();

    // Attention @ V
    dim3 gAV(1, NT/64, B*H);
    av_kernel<<<gAV, 256>>>();

    // Output projection -> out[0 .. 4194303]
    gemm_nt<<<gProj, 256>>>(pCtx, Wo, bo, out, M, DM, DM, 0);

    // Certainty -> out[4194304 .. 4198399]
    cert_kernel<<<(B*NT)/256, 256>>>(cert, ctemp, out + (size_t)M*DM);

    // Sinkhorn
    build_P_kernel<<<(B*NT*NT)/256, 256>>>();
    for (int it = 0; it < 10; it++) {
        rownorm_kernel<<<B*NT, 256>>>();
        colsum_kernel<<<dim3(NT/256, B), 256>>>();
        coldiv_kernel<<<(B*NT*NT)/256, 256>>>();
    }

    // Argmax + gather -> out[4198400 .. 4202495]
    argmax_gather_kernel<<<B*NT, 256>>>(perm, out + (size_t)M*DM + B*NT);
}